// round 2
// baseline (speedup 1.0000x reference)
#include <cuda_runtime.h>
#include <cstdint>

#define NN 100000
#define NE 600000
#define DD 128
#define NL 4

// ---------------- scratch (device globals; no allocation allowed) ----------
__device__ float g_h[NN * DD];     // running node features
__device__ float g_agg[NN * DD];   // (1+eps)*h + segment_sum(messages)
__device__ float g_y[NN * DD];     // GEMM1 output (pre-BN)
__device__ float g_sum[DD];
__device__ float g_sumsq[DD];
__device__ float g_scale[DD];
__device__ float g_shift[DD];

__device__ __forceinline__ float relu(float v) { return fmaxf(v, 0.0f); }

// ---------------- kernel 1: agg = (1+eps_l) * h_in; zero BN stats ----------
__global__ void init_agg_kernel(const float4* __restrict__ h_in,
                                const float* __restrict__ eps, int l) {
    int i = blockIdx.x * blockDim.x + threadIdx.x;
    if (i < DD) { g_sum[i] = 0.0f; g_sumsq[i] = 0.0f; }
    if (i < NN * DD / 4) {
        float s = 1.0f + eps[l];
        float4 v = h_in[i];
        v.x *= s; v.y *= s; v.z *= s; v.w *= s;
        reinterpret_cast<float4*>(g_agg)[i] = v;
    }
}

// ---------------- kernel 2: edges: agg[dst] += relu(h[src] + ea*We + be) ---
// one warp per edge; lane handles 4 consecutive floats (32*4 = 128 = D)
__global__ void edge_kernel(const float* __restrict__ h_in,
                            const int* __restrict__ src,
                            const int* __restrict__ dst,
                            const float* __restrict__ ea,
                            const float* __restrict__ We,
                            const float* __restrict__ be) {
    int e = blockIdx.x * (blockDim.x >> 5) + (threadIdx.x >> 5);
    int lane = threadIdx.x & 31;
    if (e >= NE) return;
    int s = src[e];
    int d = dst[e];
    float a = ea[e];
    const float4 h4 = *reinterpret_cast<const float4*>(h_in + (size_t)s * DD + lane * 4);
    const float4 w4 = *reinterpret_cast<const float4*>(We + lane * 4);
    const float4 b4 = *reinterpret_cast<const float4*>(be + lane * 4);
    float mx = relu(h4.x + fmaf(a, w4.x, b4.x));
    float my = relu(h4.y + fmaf(a, w4.y, b4.y));
    float mz = relu(h4.z + fmaf(a, w4.z, b4.z));
    float mw = relu(h4.w + fmaf(a, w4.w, b4.w));
    float* p = g_agg + (size_t)d * DD + lane * 4;
    atomicAdd(p + 0, mx);
    atomicAdd(p + 1, my);
    atomicAdd(p + 2, mz);
    atomicAdd(p + 3, mw);
}

// ---------------- GEMM: 64 rows/block, full 128x128 W in smem -------------
// MODE 0: Y = X @ W + b           (X = g_agg), accumulate column sum/sumsq
// MODE 1: U = relu(X*scale+shift) (X = g_y, BN applied on load)
//         O = U @ W + b ; R = relu(O) ; out = add_prev ? h_prev + R : R
template <int MODE>
__global__ void gemm_kernel(const float* __restrict__ X,
                            const float* __restrict__ W,
                            const float* __restrict__ bias,
                            const float* __restrict__ h_prev,
                            float* __restrict__ out,
                            int add_prev) {
    extern __shared__ float sm[];
    float* Ws = sm;            // 128*128
    float* Xs = sm + DD * DD;  // 64*128

    const int tid = threadIdx.x;            // 256 threads
    const int row0 = blockIdx.x * 64;

    // load W (coalesced float4)
    for (int i = tid; i < DD * DD / 4; i += 256)
        reinterpret_cast<float4*>(Ws)[i] = reinterpret_cast<const float4*>(W)[i];

    // load X tile, with BN+relu transform for MODE 1
    for (int i = tid; i < 64 * DD / 4; i += 256) {
        int r = i >> 5;         // row within tile
        int c4 = i & 31;        // float4 column index
        int grow = row0 + r;
        float4 v = make_float4(0.f, 0.f, 0.f, 0.f);
        if (grow < NN) {
            v = reinterpret_cast<const float4*>(X + (size_t)grow * DD)[c4];
            if (MODE == 1) {
                float4 sc = reinterpret_cast<const float4*>(g_scale)[c4];
                float4 sh = reinterpret_cast<const float4*>(g_shift)[c4];
                v.x = relu(fmaf(v.x, sc.x, sh.x));
                v.y = relu(fmaf(v.y, sc.y, sh.y));
                v.z = relu(fmaf(v.z, sc.z, sh.z));
                v.w = relu(fmaf(v.w, sc.w, sh.w));
            }
        }
        reinterpret_cast<float4*>(Xs)[i] = v;
    }
    __syncthreads();

    const int tcol = tid & 31;   // -> 4 output cols
    const int trow = tid >> 5;   // -> 8 output rows
    const int c0 = tcol * 4;
    const int r0 = trow * 8;

    float acc[8][4];
#pragma unroll
    for (int i = 0; i < 8; i++)
#pragma unroll
        for (int j = 0; j < 4; j++) acc[i][j] = 0.0f;

#pragma unroll 8
    for (int k = 0; k < DD; k++) {
        float4 b = reinterpret_cast<const float4*>(Ws + k * DD)[tcol];
#pragma unroll
        for (int i = 0; i < 8; i++) {
            float a = Xs[(r0 + i) * DD + k];
            acc[i][0] = fmaf(a, b.x, acc[i][0]);
            acc[i][1] = fmaf(a, b.y, acc[i][1]);
            acc[i][2] = fmaf(a, b.z, acc[i][2]);
            acc[i][3] = fmaf(a, b.w, acc[i][3]);
        }
    }

    float4 bi = reinterpret_cast<const float4*>(bias)[tcol];

    float psum[4] = {0.f, 0.f, 0.f, 0.f};
    float psq[4]  = {0.f, 0.f, 0.f, 0.f};

#pragma unroll
    for (int i = 0; i < 8; i++) {
        int grow = row0 + r0 + i;
        if (grow >= NN) continue;
        float4 o;
        o.x = acc[i][0] + bi.x;
        o.y = acc[i][1] + bi.y;
        o.z = acc[i][2] + bi.z;
        o.w = acc[i][3] + bi.w;
        if (MODE == 0) {
            reinterpret_cast<float4*>(out + (size_t)grow * DD)[tcol] = o;
            psum[0] += o.x; psq[0] += o.x * o.x;
            psum[1] += o.y; psq[1] += o.y * o.y;
            psum[2] += o.z; psq[2] += o.z * o.z;
            psum[3] += o.w; psq[3] += o.w * o.w;
        } else {
            o.x = relu(o.x); o.y = relu(o.y); o.z = relu(o.z); o.w = relu(o.w);
            if (add_prev) {
                float4 hp = reinterpret_cast<const float4*>(h_prev + (size_t)grow * DD)[tcol];
                o.x += hp.x; o.y += hp.y; o.z += hp.z; o.w += hp.w;
            }
            reinterpret_cast<float4*>(out + (size_t)grow * DD)[tcol] = o;
        }
    }

    if (MODE == 0) {
        // block reduction of column sums via shared, then one global atomic per col
        __syncthreads();                  // everyone done reading Ws/Xs
        if (tid < DD) { sm[tid] = 0.0f; sm[DD + tid] = 0.0f; }
        __syncthreads();
#pragma unroll
        for (int j = 0; j < 4; j++) {
            atomicAdd(&sm[c0 + j], psum[j]);
            atomicAdd(&sm[DD + c0 + j], psq[j]);
        }
        __syncthreads();
        if (tid < DD) {
            atomicAdd(&g_sum[tid], sm[tid]);
            atomicAdd(&g_sumsq[tid], sm[DD + tid]);
        }
    }
}

// ---------------- BN finalize: scale/shift from accumulated stats ----------
__global__ void bn_finalize_kernel(const float* __restrict__ gamma,
                                   const float* __restrict__ beta) {
    int d = threadIdx.x;
    float mu = g_sum[d] * (1.0f / NN);
    float var = g_sumsq[d] * (1.0f / NN) - mu * mu;
    float rs = rsqrtf(var + 1e-5f);
    float sc = gamma[d] * rs;
    g_scale[d] = sc;
    g_shift[d] = fmaf(-mu, sc, beta[d]);
}

// ---------------- launch ---------------------------------------------------
extern "C" void kernel_launch(void* const* d_in, const int* in_sizes, int n_in,
                              void* d_out, int out_size) {
    const float* x        = (const float*)d_in[0];
    const int* ei         = (const int*)d_in[1];         // [2, E] int32 (JAX x64 off)
    const float* ea       = (const float*)d_in[2];
    const float* We       = (const float*)d_in[3];       // [L, 1, D]
    const float* be       = (const float*)d_in[4];       // [L, D]
    const float* eps      = (const float*)d_in[5];       // [L]
    const float* W1       = (const float*)d_in[6];       // [L, D, D]
    const float* b1       = (const float*)d_in[7];
    const float* gamma    = (const float*)d_in[8];
    const float* beta     = (const float*)d_in[9];
    const float* W2       = (const float*)d_in[10];
    const float* b2       = (const float*)d_in[11];
    float* out            = (float*)d_out;

    float *hbuf, *aggbuf, *ybuf;
    cudaGetSymbolAddress((void**)&hbuf, g_h);
    cudaGetSymbolAddress((void**)&aggbuf, g_agg);
    cudaGetSymbolAddress((void**)&ybuf, g_y);

    const int SMEM = (DD * DD + 64 * DD) * sizeof(float);  // 96 KB
    cudaFuncSetAttribute(gemm_kernel<0>, cudaFuncAttributeMaxDynamicSharedMemorySize, SMEM);
    cudaFuncSetAttribute(gemm_kernel<1>, cudaFuncAttributeMaxDynamicSharedMemorySize, SMEM);

    const int* src = ei;
    const int* dst = ei + NE;

    const int initBlocks = (NN * DD / 4 + 255) / 256;     // 12500
    const int edgeBlocks = (NE + 7) / 8;                  // 75000
    const int gemmBlocks = (NN + 63) / 64;                // 1563

    for (int l = 0; l < NL; l++) {
        const float* h_in = (l == 0) ? x : hbuf;
        float* h_out = (l == NL - 1) ? out : hbuf;

        init_agg_kernel<<<initBlocks, 256>>>(
            reinterpret_cast<const float4*>(h_in), eps, l);

        edge_kernel<<<edgeBlocks, 256>>>(h_in, src, dst, ea,
                                         We + l * DD, be + l * DD);

        gemm_kernel<0><<<gemmBlocks, 256, SMEM>>>(
            aggbuf, W1 + (size_t)l * DD * DD, b1 + l * DD, nullptr, ybuf, 0);

        bn_finalize_kernel<<<1, DD>>>(gamma + l * DD, beta + l * DD);

        gemm_kernel<1><<<gemmBlocks, 256, SMEM>>>(
            ybuf, W2 + (size_t)l * DD * DD, b2 + l * DD, hbuf, h_out,
            (l > 0) ? 1 : 0);
    }
}

// round 6
// speedup vs baseline: 1.5640x; 1.5640x over previous
#include <cuda_runtime.h>
#include <cuda_bf16.h>
#include <cstdint>

#define NN 100000
#define NE 600000
#define DD 128
#define NL 4
#define NT 782            // ceil(NN/128)

// ---------------- scratch (device globals) ---------------------------------
__device__ float g_h[NN * DD];
__device__ float g_agg[NN * DD];
__device__ float g_y[NN * DD];
__device__ float g_sum[DD];
__device__ float g_sumsq[DD];
__device__ float g_scale[DD];
__device__ float g_shift[DD];

__device__ __forceinline__ float relu(float v) { return fmaxf(v, 0.0f); }

__device__ __forceinline__ uint32_t smem_u32(const void* p) {
    uint32_t a;
    asm("{ .reg .u64 t; cvta.to.shared.u64 t, %1; cvt.u32.u64 %0, t; }" : "=r"(a) : "l"(p));
    return a;
}

// split two fp32 into packed bf16x2 hi and lo
__device__ __forceinline__ void split2(float x, float y, uint32_t& h, uint32_t& l) {
    __nv_bfloat16 hx = __float2bfloat16_rn(x), hy = __float2bfloat16_rn(y);
    __nv_bfloat16 lx = __float2bfloat16_rn(x - __bfloat162float(hx));
    __nv_bfloat16 ly = __float2bfloat16_rn(y - __bfloat162float(hy));
    __nv_bfloat162 hp = __halves2bfloat162(hx, hy);
    __nv_bfloat162 lp = __halves2bfloat162(lx, ly);
    h = *reinterpret_cast<uint32_t*>(&hp);
    l = *reinterpret_cast<uint32_t*>(&lp);
}

#define LDSM_X4(r, a) \
    asm volatile("ldmatrix.sync.aligned.m8n8.x4.shared.b16 {%0,%1,%2,%3}, [%4];" \
        : "=r"((r)[0]), "=r"((r)[1]), "=r"((r)[2]), "=r"((r)[3]) : "r"(a))

#define LDSM_X4_T(r, a) \
    asm volatile("ldmatrix.sync.aligned.m8n8.x4.trans.shared.b16 {%0,%1,%2,%3}, [%4];" \
        : "=r"((r)[0]), "=r"((r)[1]), "=r"((r)[2]), "=r"((r)[3]) : "r"(a))

#define MMA_BF16(c, a, b0, b1) \
    asm volatile("mma.sync.aligned.m16n8k16.row.col.f32.bf16.bf16.f32 " \
        "{%0,%1,%2,%3},{%4,%5,%6,%7},{%8,%9},{%0,%1,%2,%3};" \
        : "+f"((c)[0]), "+f"((c)[1]), "+f"((c)[2]), "+f"((c)[3]) \
        : "r"((a)[0]), "r"((a)[1]), "r"((a)[2]), "r"((a)[3]), "r"(b0), "r"(b1))

// ---------------- kernel: agg = (1+eps)*h; zero BN stats -------------------
__global__ void init_agg_kernel(const float4* __restrict__ h_in,
                                const float* __restrict__ eps, int l) {
    int i = blockIdx.x * blockDim.x + threadIdx.x;
    if (i < DD) { g_sum[i] = 0.0f; g_sumsq[i] = 0.0f; }
    if (i < NN * DD / 4) {
        float s = 1.0f + eps[l];
        float4 v = h_in[i];
        v.x *= s; v.y *= s; v.z *= s; v.w *= s;
        reinterpret_cast<float4*>(g_agg)[i] = v;
    }
}

// ---------------- edge kernel ----------------------------------------------
__global__ void edge_kernel(const float* __restrict__ h_in,
                            const int* __restrict__ src,
                            const int* __restrict__ dst,
                            const float* __restrict__ ea,
                            const float* __restrict__ We,
                            const float* __restrict__ be) {
    int e = blockIdx.x * (blockDim.x >> 5) + (threadIdx.x >> 5);
    int lane = threadIdx.x & 31;
    if (e >= NE) return;
    int s = src[e];
    int d = dst[e];
    float a = ea[e];
    const float4 h4 = *reinterpret_cast<const float4*>(h_in + (size_t)s * DD + lane * 4);
    const float4 w4 = *reinterpret_cast<const float4*>(We + lane * 4);
    const float4 b4 = *reinterpret_cast<const float4*>(be + lane * 4);
    float mx = relu(h4.x + fmaf(a, w4.x, b4.x));
    float my = relu(h4.y + fmaf(a, w4.y, b4.y));
    float mz = relu(h4.z + fmaf(a, w4.z, b4.z));
    float mw = relu(h4.w + fmaf(a, w4.w, b4.w));
    float* p = g_agg + (size_t)d * DD + lane * 4;
    asm volatile("red.global.add.v4.f32 [%0], {%1, %2, %3, %4};"
                 :: "l"(p), "f"(mx), "f"(my), "f"(mz), "f"(mw) : "memory");
}

// ---------------- HMMA GEMM ------------------------------------------------
// X[128-tile rows][128] @ W[128][128] with hi/lo bf16 split, fp32 accum.
// MODE 0: out = X@W + b                       (X = agg, out = y)
// MODE 1: Xn = relu(X*scale+shift) [BN on load]; out = relu(Xn@W+b) (+h_prev)
// smem: padded row stride 136 bf16 = 272B (conflict-free for ldmatrix)
#define RS 272
#define BUF 34816                 // 128*272
#define SMEM_BYTES (4 * BUF)      // Ahi, Alo, Whi, Wlo

template <int MODE>
__global__ void __launch_bounds__(256, 1) gemm_hmma_kernel(
        const float* __restrict__ X,
        const float* __restrict__ W,
        const float* __restrict__ bias,
        const float* __restrict__ h_prev,
        float* __restrict__ out,
        int add_prev) {
    extern __shared__ __align__(16) char smem[];
    char* Ahi = smem;
    char* Whi = smem + 2 * BUF;
    const int tid = threadIdx.x;       // 256
    const int tile = blockIdx.x;

    // ---- fill A (with BN+relu for MODE 1) and W, split hi/lo ----
    for (int i = tid; i < 4096; i += 256) {
        int r = i >> 5, c4 = i & 31;
        // A
        {
            int grow = tile * 128 + r;
            float4 v = make_float4(0.f, 0.f, 0.f, 0.f);
            if (grow < NN) {
                v = reinterpret_cast<const float4*>(X + (size_t)grow * DD)[c4];
                if (MODE == 1) {
                    float4 sc = reinterpret_cast<const float4*>(g_scale)[c4];
                    float4 sh = reinterpret_cast<const float4*>(g_shift)[c4];
                    v.x = relu(fmaf(v.x, sc.x, sh.x));
                    v.y = relu(fmaf(v.y, sc.y, sh.y));
                    v.z = relu(fmaf(v.z, sc.z, sh.z));
                    v.w = relu(fmaf(v.w, sc.w, sh.w));
                }
            }
            uint2 h2, l2;
            split2(v.x, v.y, h2.x, l2.x);
            split2(v.z, v.w, h2.y, l2.y);
            *reinterpret_cast<uint2*>(Ahi + r * RS + c4 * 8) = h2;
            *reinterpret_cast<uint2*>(Ahi + BUF + r * RS + c4 * 8) = l2;
        }
        // W (row-major [k][n])
        {
            float4 v = reinterpret_cast<const float4*>(W + (size_t)r * DD)[c4];
            uint2 h2, l2;
            split2(v.x, v.y, h2.x, l2.x);
            split2(v.z, v.w, h2.y, l2.y);
            *reinterpret_cast<uint2*>(Whi + r * RS + c4 * 8) = h2;
            *reinterpret_cast<uint2*>(Whi + BUF + r * RS + c4 * 8) = l2;
        }
    }
    __syncthreads();

    const int wid = tid >> 5;
    const int lane = tid & 31;
    const int warp_m = wid & 3;        // 4 x 32 rows
    const int warp_n = wid >> 2;       // 2 x 64 cols
    const int j = lane >> 3;
    const int rr = lane & 7;
    const uint32_t sA = smem_u32(Ahi);
    const uint32_t sW = smem_u32(Whi);

    // ldmatrix lane addresses
    uint32_t aaddr[2];
#pragma unroll
    for (int mt = 0; mt < 2; mt++)
        aaddr[mt] = sA + (uint32_t)((warp_m * 32 + mt * 16 + (j & 1) * 8 + rr) * RS + (j >> 1) * 16);
    uint32_t baddr[4];
#pragma unroll
    for (int p = 0; p < 4; p++)
        baddr[p] = sW + (uint32_t)(((j & 1) * 8 + rr) * RS + (warp_n * 64 + p * 16 + (j >> 1) * 8) * 2);

    float acc[2][8][4];
#pragma unroll
    for (int mt = 0; mt < 2; mt++)
#pragma unroll
        for (int nt = 0; nt < 8; nt++)
#pragma unroll
            for (int q = 0; q < 4; q++) acc[mt][nt][q] = 0.0f;

#pragma unroll
    for (int ks = 0; ks < 8; ks++) {
        uint32_t ah[2][4], al[2][4], bh[4][4], bl[4][4];
#pragma unroll
        for (int mt = 0; mt < 2; mt++) {
            LDSM_X4(ah[mt], aaddr[mt]);
            LDSM_X4(al[mt], aaddr[mt] + BUF);
            aaddr[mt] += 32;                    // k += 16 elems
        }
#pragma unroll
        for (int p = 0; p < 4; p++) {
            LDSM_X4_T(bh[p], baddr[p]);
            LDSM_X4_T(bl[p], baddr[p] + BUF);
            baddr[p] += 16 * RS;                // k rows += 16
        }
#pragma unroll
        for (int mt = 0; mt < 2; mt++)
#pragma unroll
            for (int nt = 0; nt < 8; nt++) {
                const int p = nt >> 1, t2 = (nt & 1) * 2;
                MMA_BF16(acc[mt][nt], ah[mt], bh[p][t2], bh[p][t2 + 1]);
                MMA_BF16(acc[mt][nt], ah[mt], bl[p][t2], bl[p][t2 + 1]);
                MMA_BF16(acc[mt][nt], al[mt], bh[p][t2], bh[p][t2 + 1]);
            }
    }

    // ---- epilogue ----
#pragma unroll
    for (int mt = 0; mt < 2; mt++) {
#pragma unroll
        for (int nt = 0; nt < 8; nt++) {
            int row = tile * 128 + warp_m * 32 + mt * 16 + (lane >> 2);
            int col = warp_n * 64 + nt * 8 + (lane & 3) * 2;
            float2 bv = *reinterpret_cast<const float2*>(bias + col);
#pragma unroll
            for (int hh = 0; hh < 2; hh++) {
                int grow = row + hh * 8;
                if (grow < NN) {
                    float2 o;
                    o.x = acc[mt][nt][hh * 2 + 0] + bv.x;
                    o.y = acc[mt][nt][hh * 2 + 1] + bv.y;
                    if (MODE == 1) {
                        o.x = relu(o.x); o.y = relu(o.y);
                        if (add_prev) {
                            float2 hp = *reinterpret_cast<const float2*>(
                                h_prev + (size_t)grow * DD + col);
                            o.x += hp.x; o.y += hp.y;
                        }
                    }
                    *reinterpret_cast<float2*>(out + (size_t)grow * DD + col) = o;
                }
            }
        }
    }
}

// ---------------- column stats over y --------------------------------------
__global__ void stats_kernel(const float* __restrict__ Y) {
    __shared__ float ssum[8][128];
    __shared__ float ssq[8][128];
    int tid = threadIdx.x;           // 256
    int c4 = tid & 31, rp = tid >> 5;
    float4 s = make_float4(0.f, 0.f, 0.f, 0.f);
    float4 q = make_float4(0.f, 0.f, 0.f, 0.f);
    for (int r = blockIdx.x * 8 + rp; r < NN; r += gridDim.x * 8) {
        float4 v = reinterpret_cast<const float4*>(Y + (size_t)r * DD)[c4];
        s.x += v.x; s.y += v.y; s.z += v.z; s.w += v.w;
        q.x += v.x * v.x; q.y += v.y * v.y; q.z += v.z * v.z; q.w += v.w * v.w;
    }
    ssum[rp][c4 * 4 + 0] = s.x; ssum[rp][c4 * 4 + 1] = s.y;
    ssum[rp][c4 * 4 + 2] = s.z; ssum[rp][c4 * 4 + 3] = s.w;
    ssq[rp][c4 * 4 + 0] = q.x;  ssq[rp][c4 * 4 + 1] = q.y;
    ssq[rp][c4 * 4 + 2] = q.z;  ssq[rp][c4 * 4 + 3] = q.w;
    __syncthreads();
    if (tid < 128) {
        float ts = 0.f, tq = 0.f;
#pragma unroll
        for (int i = 0; i < 8; i++) { ts += ssum[i][tid]; tq += ssq[i][tid]; }
        atomicAdd(&g_sum[tid], ts);
        atomicAdd(&g_sumsq[tid], tq);
    }
}

// ---------------- BN finalize ----------------------------------------------
__global__ void bn_finalize_kernel(const float* __restrict__ gamma,
                                   const float* __restrict__ beta) {
    int d = threadIdx.x;
    float mu = g_sum[d] * (1.0f / NN);
    float var = g_sumsq[d] * (1.0f / NN) - mu * mu;
    float rs = rsqrtf(var + 1e-5f);
    float sc = gamma[d] * rs;
    g_scale[d] = sc;
    g_shift[d] = fmaf(-mu, sc, beta[d]);
}

// ---------------- launch ---------------------------------------------------
extern "C" void kernel_launch(void* const* d_in, const int* in_sizes, int n_in,
                              void* d_out, int out_size) {
    const float* x     = (const float*)d_in[0];
    const int* ei      = (const int*)d_in[1];
    const float* ea    = (const float*)d_in[2];
    const float* We    = (const float*)d_in[3];
    const float* be    = (const float*)d_in[4];
    const float* eps   = (const float*)d_in[5];
    const float* W1    = (const float*)d_in[6];
    const float* b1    = (const float*)d_in[7];
    const float* gamma = (const float*)d_in[8];
    const float* beta  = (const float*)d_in[9];
    const float* W2    = (const float*)d_in[10];
    const float* b2    = (const float*)d_in[11];
    float* out         = (float*)d_out;

    float *hbuf, *aggbuf, *ybuf;
    cudaGetSymbolAddress((void**)&hbuf, g_h);
    cudaGetSymbolAddress((void**)&aggbuf, g_agg);
    cudaGetSymbolAddress((void**)&ybuf, g_y);

    cudaFuncSetAttribute(gemm_hmma_kernel<0>, cudaFuncAttributeMaxDynamicSharedMemorySize, SMEM_BYTES);
    cudaFuncSetAttribute(gemm_hmma_kernel<1>, cudaFuncAttributeMaxDynamicSharedMemorySize, SMEM_BYTES);

    const int* src = ei;
    const int* dst = ei + NE;

    const int initBlocks = (NN * DD / 4 + 255) / 256;
    const int edgeBlocks = (NE + 7) / 8;

    for (int l = 0; l < NL; l++) {
        const float* h_in = (l == 0) ? x : hbuf;
        float* h_out = (l == NL - 1) ? out : hbuf;

        init_agg_kernel<<<initBlocks, 256>>>(
            reinterpret_cast<const float4*>(h_in), eps, l);

        edge_kernel<<<edgeBlocks, 256>>>(h_in, src, dst, ea,
                                         We + l * DD, be + l * DD);

        gemm_hmma_kernel<0><<<NT, 256, SMEM_BYTES>>>(
            aggbuf, W1 + (size_t)l * DD * DD, b1 + l * DD, nullptr, ybuf, 0);

        stats_kernel<<<256, 256>>>(ybuf);

        bn_finalize_kernel<<<1, DD>>>(gamma + l * DD, beta + l * DD);

        gemm_hmma_kernel<1><<<NT, 256, SMEM_BYTES>>>(
            ybuf, W2 + (size_t)l * DD * DD, b2 + l * DD, hbuf, h_out,
            (l > 0) ? 1 : 0);
    }
}

// round 7
// speedup vs baseline: 1.8185x; 1.1627x over previous
#include <cuda_runtime.h>
#include <cuda_bf16.h>
#include <cstdint>

#define NN 100000
#define NE 600000
#define DD 128
#define NL 4
#define NT 782            // ceil(NN/128)

// ---------------- scratch (device globals) ---------------------------------
__device__ float g_h[NN * DD];
__device__ float g_y[NN * DD];
__device__ float g_sum[DD];
__device__ float g_sumsq[DD];
__device__ float g_scale[DD];
__device__ float g_shift[DD];
__device__ int   g_cnt[NN];
__device__ int   g_off[NN + 1];
__device__ int   g_bsum[512];
__device__ int   g_cur[NN];
__device__ uint2 g_edges[NE];   // (src, ea bits) sorted by dst

__device__ __forceinline__ float relu(float v) { return fmaxf(v, 0.0f); }

__device__ __forceinline__ uint32_t smem_u32(const void* p) {
    uint32_t a;
    asm("{ .reg .u64 t; cvta.to.shared.u64 t, %1; cvt.u32.u64 %0, t; }" : "=r"(a) : "l"(p));
    return a;
}

__device__ __forceinline__ void split2(float x, float y, uint32_t& h, uint32_t& l) {
    __nv_bfloat16 hx = __float2bfloat16_rn(x), hy = __float2bfloat16_rn(y);
    __nv_bfloat16 lx = __float2bfloat16_rn(x - __bfloat162float(hx));
    __nv_bfloat16 ly = __float2bfloat16_rn(y - __bfloat162float(hy));
    __nv_bfloat162 hp = __halves2bfloat162(hx, hy);
    __nv_bfloat162 lp = __halves2bfloat162(lx, ly);
    h = *reinterpret_cast<uint32_t*>(&hp);
    l = *reinterpret_cast<uint32_t*>(&lp);
}

#define LDSM_X4(r, a) \
    asm volatile("ldmatrix.sync.aligned.m8n8.x4.shared.b16 {%0,%1,%2,%3}, [%4];" \
        : "=r"((r)[0]), "=r"((r)[1]), "=r"((r)[2]), "=r"((r)[3]) : "r"(a))

#define LDSM_X4_T(r, a) \
    asm volatile("ldmatrix.sync.aligned.m8n8.x4.trans.shared.b16 {%0,%1,%2,%3}, [%4];" \
        : "=r"((r)[0]), "=r"((r)[1]), "=r"((r)[2]), "=r"((r)[3]) : "r"(a))

#define MMA_BF16(c, a, b0, b1) \
    asm volatile("mma.sync.aligned.m16n8k16.row.col.f32.bf16.bf16.f32 " \
        "{%0,%1,%2,%3},{%4,%5,%6,%7},{%8,%9},{%0,%1,%2,%3};" \
        : "+f"((c)[0]), "+f"((c)[1]), "+f"((c)[2]), "+f"((c)[3]) \
        : "r"((a)[0]), "r"((a)[1]), "r"((a)[2]), "r"((a)[3]), "r"(b0), "r"(b1))

// =================== CSR preprocessing (once per launch) ====================
__global__ void k_zero() {
    int i = blockIdx.x * blockDim.x + threadIdx.x;
    if (i < NN) g_cnt[i] = 0;
    if (i < DD) { g_sum[i] = 0.0f; g_sumsq[i] = 0.0f; }
}
__global__ void k_hist(const int* __restrict__ dst) {
    int e = blockIdx.x * blockDim.x + threadIdx.x;
    if (e < NE) atomicAdd(&g_cnt[dst[e]], 1);
}
__global__ void k_scan1() {
    __shared__ int sh[256];
    int t = threadIdx.x;
    int i = blockIdx.x * 256 + t;
    int v = (i < NN) ? g_cnt[i] : 0;
    sh[t] = v;
    __syncthreads();
    for (int s = 1; s < 256; s <<= 1) {
        int u = (t >= s) ? sh[t - s] : 0;
        __syncthreads();
        sh[t] += u;
        __syncthreads();
    }
    if (i < NN) g_off[i] = sh[t] - v;        // exclusive within block
    if (t == 255) g_bsum[blockIdx.x] = sh[255];
}
__global__ void k_scan2(int nblk) {
    __shared__ int sh[512];
    int t = threadIdx.x;
    int v = (t < nblk) ? g_bsum[t] : 0;
    sh[t] = v;
    __syncthreads();
    for (int s = 1; s < 512; s <<= 1) {
        int u = (t >= s) ? sh[t - s] : 0;
        __syncthreads();
        sh[t] += u;
        __syncthreads();
    }
    if (t < nblk) g_bsum[t] = sh[t] - v;     // exclusive
}
__global__ void k_apply() {
    int i = blockIdx.x * blockDim.x + threadIdx.x;
    if (i < NN) {
        g_off[i] += g_bsum[i >> 8];
        g_cur[i] = 0;
    }
    if (i == 0) g_off[NN] = NE;
}
__global__ void k_fill(const int* __restrict__ src, const int* __restrict__ dst,
                       const float* __restrict__ ea) {
    int e = blockIdx.x * blockDim.x + threadIdx.x;
    if (e >= NE) return;
    int d = dst[e];
    int pos = g_off[d] + atomicAdd(&g_cur[d], 1);
    g_edges[pos] = make_uint2((uint32_t)src[e], __float_as_uint(ea[e]));
}

// =================== HMMA GEMM =============================================
// MODE 0: A = (1+eps)*h + sum_{edges} relu(h[src]+ea*We+be)  (built in smem)
//         out = A@W1 + b1 -> y ; accumulate column sum/sumsq stats
// MODE 1: A = relu(y*scale+shift) ; out = relu(A@W2+b2) (+ h_prev)
#define RS 272
#define BUF 34816                 // 128*272
#define SMEM_BYTES (4 * BUF)

template <int MODE>
__global__ void __launch_bounds__(512, 1) gemm_hmma_kernel(
        const float* __restrict__ Xin,        // h_in (MODE0) or y (MODE1)
        const float* __restrict__ W,
        const float* __restrict__ bias,
        const float* __restrict__ h_prev,
        float* __restrict__ out,
        int add_prev,
        const float* __restrict__ eps, int l,
        const float* __restrict__ We, const float* __restrict__ be) {
    extern __shared__ __align__(16) char smem[];
    char* Ahi = smem;
    char* Whi = smem + 2 * BUF;
    const int tid = threadIdx.x;       // 512
    const int tile = blockIdx.x;
    const int wid = tid >> 5;
    const int lane = tid & 31;

    // ---- W fill (both modes) ----
    for (int i = tid; i < 4096; i += 512) {
        int r = i >> 5, c4 = i & 31;
        float4 v = reinterpret_cast<const float4*>(W + (size_t)r * DD)[c4];
        uint2 h2, l2;
        split2(v.x, v.y, h2.x, l2.x);
        split2(v.z, v.w, h2.y, l2.y);
        *reinterpret_cast<uint2*>(Whi + r * RS + c4 * 8) = h2;
        *reinterpret_cast<uint2*>(Whi + BUF + r * RS + c4 * 8) = l2;
    }

    // ---- A fill ----
    if (MODE == 0) {
        // fused aggregation: warp per row, 8 rows per warp
        const float4* X4 = reinterpret_cast<const float4*>(Xin);
        float4 w4 = reinterpret_cast<const float4*>(We)[lane];
        float4 b4 = reinterpret_cast<const float4*>(be)[lane];
        float s1 = 1.0f + eps[l];
        for (int rr2 = 0; rr2 < 8; rr2++) {
            int r = wid * 8 + rr2;
            int n = tile * 128 + r;
            float4 acc = make_float4(0.f, 0.f, 0.f, 0.f);
            if (n < NN) {
                float4 hv = X4[(size_t)n * 32 + lane];
                acc.x = s1 * hv.x; acc.y = s1 * hv.y;
                acc.z = s1 * hv.z; acc.w = s1 * hv.w;
                int base = g_off[n];
                int deg = g_off[n + 1] - base;
                int i = 0;
                for (; i + 2 <= deg; i += 2) {
                    uint2 e0 = g_edges[base + i];
                    uint2 e1 = g_edges[base + i + 1];
                    float4 h0 = X4[(size_t)e0.x * 32 + lane];
                    float4 h1 = X4[(size_t)e1.x * 32 + lane];
                    float a0 = __uint_as_float(e0.y);
                    float a1 = __uint_as_float(e1.y);
                    acc.x += relu(h0.x + fmaf(a0, w4.x, b4.x)) + relu(h1.x + fmaf(a1, w4.x, b4.x));
                    acc.y += relu(h0.y + fmaf(a0, w4.y, b4.y)) + relu(h1.y + fmaf(a1, w4.y, b4.y));
                    acc.z += relu(h0.z + fmaf(a0, w4.z, b4.z)) + relu(h1.z + fmaf(a1, w4.z, b4.z));
                    acc.w += relu(h0.w + fmaf(a0, w4.w, b4.w)) + relu(h1.w + fmaf(a1, w4.w, b4.w));
                }
                if (i < deg) {
                    uint2 e0 = g_edges[base + i];
                    float4 h0 = X4[(size_t)e0.x * 32 + lane];
                    float a0 = __uint_as_float(e0.y);
                    acc.x += relu(h0.x + fmaf(a0, w4.x, b4.x));
                    acc.y += relu(h0.y + fmaf(a0, w4.y, b4.y));
                    acc.z += relu(h0.z + fmaf(a0, w4.z, b4.z));
                    acc.w += relu(h0.w + fmaf(a0, w4.w, b4.w));
                }
            }
            uint2 h2, l2;
            split2(acc.x, acc.y, h2.x, l2.x);
            split2(acc.z, acc.w, h2.y, l2.y);
            *reinterpret_cast<uint2*>(Ahi + r * RS + lane * 8) = h2;
            *reinterpret_cast<uint2*>(Ahi + BUF + r * RS + lane * 8) = l2;
        }
    } else {
        for (int i = tid; i < 4096; i += 512) {
            int r = i >> 5, c4 = i & 31;
            int grow = tile * 128 + r;
            float4 v = make_float4(0.f, 0.f, 0.f, 0.f);
            if (grow < NN) {
                v = reinterpret_cast<const float4*>(Xin + (size_t)grow * DD)[c4];
                float4 sc = reinterpret_cast<const float4*>(g_scale)[c4];
                float4 sh = reinterpret_cast<const float4*>(g_shift)[c4];
                v.x = relu(fmaf(v.x, sc.x, sh.x));
                v.y = relu(fmaf(v.y, sc.y, sh.y));
                v.z = relu(fmaf(v.z, sc.z, sh.z));
                v.w = relu(fmaf(v.w, sc.w, sh.w));
            }
            uint2 h2, l2;
            split2(v.x, v.y, h2.x, l2.x);
            split2(v.z, v.w, h2.y, l2.y);
            *reinterpret_cast<uint2*>(Ahi + r * RS + c4 * 8) = h2;
            *reinterpret_cast<uint2*>(Ahi + BUF + r * RS + c4 * 8) = l2;
        }
    }
    __syncthreads();

    // ---- MMA: 16 warps, each 32 rows x 32 cols ----
    const int warp_m = wid & 3;
    const int warp_n = wid >> 2;
    const int j = lane >> 3;
    const int rr = lane & 7;
    const uint32_t sA = smem_u32(Ahi);
    const uint32_t sW = smem_u32(Whi);

    uint32_t aaddr[2];
#pragma unroll
    for (int mt = 0; mt < 2; mt++)
        aaddr[mt] = sA + (uint32_t)((warp_m * 32 + mt * 16 + (j & 1) * 8 + rr) * RS + (j >> 1) * 16);
    uint32_t baddr[2];
#pragma unroll
    for (int p = 0; p < 2; p++)
        baddr[p] = sW + (uint32_t)(((j & 1) * 8 + rr) * RS + (warp_n * 32 + p * 16 + (j >> 1) * 8) * 2);

    float acc[2][4][4];
#pragma unroll
    for (int mt = 0; mt < 2; mt++)
#pragma unroll
        for (int nt = 0; nt < 4; nt++)
#pragma unroll
            for (int q = 0; q < 4; q++) acc[mt][nt][q] = 0.0f;

#pragma unroll
    for (int ks = 0; ks < 8; ks++) {
        uint32_t ah[2][4], al[2][4], bh[2][4], bl[2][4];
#pragma unroll
        for (int mt = 0; mt < 2; mt++) {
            LDSM_X4(ah[mt], aaddr[mt]);
            LDSM_X4(al[mt], aaddr[mt] + BUF);
            aaddr[mt] += 32;
        }
#pragma unroll
        for (int p = 0; p < 2; p++) {
            LDSM_X4_T(bh[p], baddr[p]);
            LDSM_X4_T(bl[p], baddr[p] + BUF);
            baddr[p] += 16 * RS;
        }
#pragma unroll
        for (int mt = 0; mt < 2; mt++)
#pragma unroll
            for (int nt = 0; nt < 4; nt++) {
                const int p = nt >> 1, t2 = (nt & 1) * 2;
                MMA_BF16(acc[mt][nt], ah[mt], bh[p][t2], bh[p][t2 + 1]);
                MMA_BF16(acc[mt][nt], ah[mt], bl[p][t2], bl[p][t2 + 1]);
                MMA_BF16(acc[mt][nt], al[mt], bh[p][t2], bh[p][t2 + 1]);
            }
    }

    // ---- epilogue ----
    float* ssum = reinterpret_cast<float*>(smem);         // [128] sum, [128] sq
    if (MODE == 0) {
        __syncthreads();                                   // smem tiles done
        if (tid < 256) ssum[tid] = 0.0f;
        __syncthreads();
    }

    float sv[8], qv[8];
#pragma unroll
    for (int i = 0; i < 8; i++) { sv[i] = 0.0f; qv[i] = 0.0f; }

#pragma unroll
    for (int mt = 0; mt < 2; mt++) {
#pragma unroll
        for (int nt = 0; nt < 4; nt++) {
            int row = tile * 128 + warp_m * 32 + mt * 16 + (lane >> 2);
            int col = warp_n * 32 + nt * 8 + (lane & 3) * 2;
            float2 bv = *reinterpret_cast<const float2*>(bias + col);
#pragma unroll
            for (int hh = 0; hh < 2; hh++) {
                int grow = row + hh * 8;
                if (grow < NN) {
                    float2 o;
                    o.x = acc[mt][nt][hh * 2 + 0] + bv.x;
                    o.y = acc[mt][nt][hh * 2 + 1] + bv.y;
                    if (MODE == 0) {
                        sv[nt * 2 + 0] += o.x; qv[nt * 2 + 0] += o.x * o.x;
                        sv[nt * 2 + 1] += o.y; qv[nt * 2 + 1] += o.y * o.y;
                    } else {
                        o.x = relu(o.x); o.y = relu(o.y);
                        if (add_prev) {
                            float2 hp = *reinterpret_cast<const float2*>(
                                h_prev + (size_t)grow * DD + col);
                            o.x += hp.x; o.y += hp.y;
                        }
                    }
                    *reinterpret_cast<float2*>(out + (size_t)grow * DD + col) = o;
                }
            }
        }
    }

    if (MODE == 0) {
        // reduce rows within warp: lanes {l, l+4, l+8, ..., l+28} share columns
#pragma unroll
        for (int i = 0; i < 8; i++) {
#pragma unroll
            for (int k = 4; k < 32; k <<= 1) {
                sv[i] += __shfl_xor_sync(0xffffffff, sv[i], k);
                qv[i] += __shfl_xor_sync(0xffffffff, qv[i], k);
            }
        }
        if (lane < 4) {
#pragma unroll
            for (int i = 0; i < 8; i++) {
                int col = warp_n * 32 + (i >> 1) * 8 + lane * 2 + (i & 1);
                atomicAdd(&ssum[col], sv[i]);
                atomicAdd(&ssum[128 + col], qv[i]);
            }
        }
        __syncthreads();
        if (tid < 128) {
            atomicAdd(&g_sum[tid], ssum[tid]);
            atomicAdd(&g_sumsq[tid], ssum[128 + tid]);
        }
    }
}

// ---------------- BN finalize (zeroes stats for next layer) ----------------
__global__ void bn_finalize_kernel(const float* __restrict__ gamma,
                                   const float* __restrict__ beta) {
    int d = threadIdx.x;
    float mu = g_sum[d] * (1.0f / NN);
    float var = g_sumsq[d] * (1.0f / NN) - mu * mu;
    float rs = rsqrtf(var + 1e-5f);
    float sc = gamma[d] * rs;
    g_scale[d] = sc;
    g_shift[d] = fmaf(-mu, sc, beta[d]);
    g_sum[d] = 0.0f;
    g_sumsq[d] = 0.0f;
}

// ---------------- launch ---------------------------------------------------
extern "C" void kernel_launch(void* const* d_in, const int* in_sizes, int n_in,
                              void* d_out, int out_size) {
    const float* x     = (const float*)d_in[0];
    const int* ei      = (const int*)d_in[1];
    const float* ea    = (const float*)d_in[2];
    const float* We    = (const float*)d_in[3];
    const float* be    = (const float*)d_in[4];
    const float* eps   = (const float*)d_in[5];
    const float* W1    = (const float*)d_in[6];
    const float* b1    = (const float*)d_in[7];
    const float* gamma = (const float*)d_in[8];
    const float* beta  = (const float*)d_in[9];
    const float* W2    = (const float*)d_in[10];
    const float* b2    = (const float*)d_in[11];
    float* out         = (float*)d_out;

    float *hbuf, *ybuf;
    cudaGetSymbolAddress((void**)&hbuf, g_h);
    cudaGetSymbolAddress((void**)&ybuf, g_y);

    cudaFuncSetAttribute(gemm_hmma_kernel<0>, cudaFuncAttributeMaxDynamicSharedMemorySize, SMEM_BYTES);
    cudaFuncSetAttribute(gemm_hmma_kernel<1>, cudaFuncAttributeMaxDynamicSharedMemorySize, SMEM_BYTES);

    const int* src = ei;
    const int* dst = ei + NE;

    // ---- CSR preprocessing (edge structure is layer-invariant) ----
    const int nblk = (NN + 255) / 256;        // 391
    k_zero<<<(NN + 1023) / 1024, 1024>>>();
    k_hist<<<(NE + 255) / 256, 256>>>(dst);
    k_scan1<<<nblk, 256>>>();
    k_scan2<<<1, 512>>>(nblk);
    k_apply<<<(NN + 1023) / 1024, 1024>>>();
    k_fill<<<(NE + 255) / 256, 256>>>(src, dst, ea);

    for (int l = 0; l < NL; l++) {
        const float* h_in = (l == 0) ? x : hbuf;
        float* h_out = (l == NL - 1) ? out : hbuf;

        gemm_hmma_kernel<0><<<NT, 512, SMEM_BYTES>>>(
            h_in, W1 + (size_t)l * DD * DD, b1 + l * DD, nullptr, ybuf, 0,
            eps, l, We + l * DD, be + l * DD);

        bn_finalize_kernel<<<1, DD>>>(gamma + l * DD, beta + l * DD);

        gemm_hmma_kernel<1><<<NT, 512, SMEM_BYTES>>>(
            ybuf, W2 + (size_t)l * DD * DD, b2 + l * DD, hbuf, h_out,
            (l > 0) ? 1 : 0, eps, l, nullptr, nullptr);
    }
}

// round 8
// speedup vs baseline: 2.0229x; 1.1124x over previous
#include <cuda_runtime.h>
#include <cuda_bf16.h>
#include <cstdint>

#define NN 100000
#define NE 600000
#define DD 128
#define NL 4
#define NT2 1563          // ceil(NN/64)

#define RS 272            // padded row stride bytes (136 bf16)
#define ABUF 17408        // 64*272
#define WBUF 34816        // 128*272
#define WMAT 69632        // hi+lo image per matrix
#define SMEM_BYTES (2 * ABUF + 2 * WBUF)   // 104448

// ---------------- scratch (device globals) ---------------------------------
__device__ float g_h[NN * DD];
__device__ float g_y[NN * DD];
__device__ float g_sumL[NL][DD];
__device__ float g_sumsqL[NL][DD];
__device__ int   g_cnt[NN];
__device__ int   g_off[NN + 1];
__device__ int   g_bsum[512];
__device__ int   g_cur[NN];
__device__ uint2 g_edges[NE];   // (src, ea bits) sorted by dst
__device__ unsigned char g_wt[8 * WMAT];   // pre-tiled bf16 hi|lo weight images

__device__ __forceinline__ float relu(float v) { return fmaxf(v, 0.0f); }

__device__ __forceinline__ uint32_t smem_u32(const void* p) {
    uint32_t a;
    asm("{ .reg .u64 t; cvta.to.shared.u64 t, %1; cvt.u32.u64 %0, t; }" : "=r"(a) : "l"(p));
    return a;
}

__device__ __forceinline__ void split2(float x, float y, uint32_t& h, uint32_t& l) {
    __nv_bfloat16 hx = __float2bfloat16_rn(x), hy = __float2bfloat16_rn(y);
    __nv_bfloat16 lx = __float2bfloat16_rn(x - __bfloat162float(hx));
    __nv_bfloat16 ly = __float2bfloat16_rn(y - __bfloat162float(hy));
    __nv_bfloat162 hp = __halves2bfloat162(hx, hy);
    __nv_bfloat162 lp = __halves2bfloat162(lx, ly);
    h = *reinterpret_cast<uint32_t*>(&hp);
    l = *reinterpret_cast<uint32_t*>(&lp);
}

#define LDSM_X4(r, a) \
    asm volatile("ldmatrix.sync.aligned.m8n8.x4.shared.b16 {%0,%1,%2,%3}, [%4];" \
        : "=r"((r)[0]), "=r"((r)[1]), "=r"((r)[2]), "=r"((r)[3]) : "r"(a))

#define LDSM_X4_T(r, a) \
    asm volatile("ldmatrix.sync.aligned.m8n8.x4.trans.shared.b16 {%0,%1,%2,%3}, [%4];" \
        : "=r"((r)[0]), "=r"((r)[1]), "=r"((r)[2]), "=r"((r)[3]) : "r"(a))

#define MMA_BF16(c, a, b0, b1) \
    asm volatile("mma.sync.aligned.m16n8k16.row.col.f32.bf16.bf16.f32 " \
        "{%0,%1,%2,%3},{%4,%5,%6,%7},{%8,%9},{%0,%1,%2,%3};" \
        : "+f"((c)[0]), "+f"((c)[1]), "+f"((c)[2]), "+f"((c)[3]) \
        : "r"((a)[0]), "r"((a)[1]), "r"((a)[2]), "r"((a)[3]), "r"(b0), "r"(b1))

#define CP_ASYNC16(d, s) \
    asm volatile("cp.async.ca.shared.global [%0], [%1], 16;" :: "r"(d), "l"(s))

// =================== preprocessing (5 launches) =============================
// k_zero: zero cnt + stats, AND pre-tile all 8 weight matrices (hi/lo, RS layout)
__global__ void k_zero(const float* __restrict__ W1, const float* __restrict__ W2) {
    int gid = blockIdx.x * blockDim.x + threadIdx.x;
    if (gid < NN) g_cnt[gid] = 0;
    if (gid < NL * DD) {
        (&g_sumL[0][0])[gid] = 0.0f;
        (&g_sumsqL[0][0])[gid] = 0.0f;
    }
    if (gid < 32768) {               // 8 matrices x 4096 float4
        int m = gid >> 12;
        int rem = gid & 4095;
        int r = rem >> 5, c4 = rem & 31;
        const float* Wsrc = ((m & 1) ? W2 : W1) + (size_t)(m >> 1) * DD * DD;
        float4 v = reinterpret_cast<const float4*>(Wsrc + (size_t)r * DD)[c4];
        uint2 h2, l2;
        split2(v.x, v.y, h2.x, l2.x);
        split2(v.z, v.w, h2.y, l2.y);
        unsigned char* base = g_wt + (size_t)m * WMAT;
        *reinterpret_cast<uint2*>(base + r * RS + c4 * 8) = h2;
        *reinterpret_cast<uint2*>(base + WBUF + r * RS + c4 * 8) = l2;
    }
}
__global__ void k_hist(const int* __restrict__ dst) {
    int e = blockIdx.x * blockDim.x + threadIdx.x;
    if (e < NE) atomicAdd(&g_cnt[dst[e]], 1);
}
__global__ void k_scan1() {
    __shared__ int sh[256];
    int t = threadIdx.x;
    int i = blockIdx.x * 256 + t;
    int v = (i < NN) ? g_cnt[i] : 0;
    sh[t] = v;
    __syncthreads();
    for (int s = 1; s < 256; s <<= 1) {
        int u = (t >= s) ? sh[t - s] : 0;
        __syncthreads();
        sh[t] += u;
        __syncthreads();
    }
    if (i < NN) g_off[i] = sh[t] - v;
    if (t == 255) g_bsum[blockIdx.x] = sh[255];
}
__global__ void k_scan2apply() {     // grid nblk, block 256
    __shared__ int sh[256];
    int b = blockIdx.x, t = threadIdx.x;
    int acc = 0;
    for (int i = t; i < b; i += 256) acc += g_bsum[i];
    sh[t] = acc;
    __syncthreads();
    for (int s = 128; s > 0; s >>= 1) {
        if (t < s) sh[t] += sh[t + s];
        __syncthreads();
    }
    int prefix = sh[0];
    int i = b * 256 + t;
    if (i < NN) { g_off[i] += prefix; g_cur[i] = 0; }
    if (b == 0 && t == 0) g_off[NN] = NE;
}
__global__ void k_fill(const int* __restrict__ src, const int* __restrict__ dst,
                       const float* __restrict__ ea) {
    int e = blockIdx.x * blockDim.x + threadIdx.x;
    if (e >= NE) return;
    int d = dst[e];
    int pos = g_off[d] + atomicAdd(&g_cur[d], 1);
    g_edges[pos] = make_uint2((uint32_t)src[e], __float_as_uint(ea[e]));
}

// =================== HMMA GEMM (64-row tiles, 256 thr, 2 CTA/SM) ===========
// MODE 0: A = (1+eps)*h + sum_edges relu(h[src]+ea*We+be); y = A@W1+b1; stats->g_sumL[l]
// MODE 1: scale/shift from g_sumL[l]; A = relu(y*sc+sh); out = relu(A@W2+b2) (+h_prev)
template <int MODE>
__global__ void __launch_bounds__(256, 2) gemm_hmma_kernel(
        const float* __restrict__ Xin,
        int widx,
        const float* __restrict__ bias,
        const float* __restrict__ h_prev,
        float* __restrict__ out,
        int add_prev,
        const float* __restrict__ eps, int l,
        const float* __restrict__ We, const float* __restrict__ be) {
    extern __shared__ __align__(16) char smem[];
    __shared__ __align__(16) float s_scale[DD];
    __shared__ __align__(16) float s_shift[DD];
    char* Ahi = smem;
    char* Whi = smem + 2 * ABUF;
    const int tid = threadIdx.x;       // 256
    const int tile = blockIdx.x;
    const int wid = tid >> 5;
    const int lane = tid & 31;

    // ---- W copy via cp.async (overlaps with A fill below) ----
    {
        const unsigned char* wsrc = g_wt + (size_t)widx * WMAT;
        uint32_t wdst = smem_u32(Whi);
#pragma unroll
        for (int i = 0; i < 17; i++) {
            int idx = i * 256 + tid;   // 4352 x 16B
            CP_ASYNC16(wdst + idx * 16, wsrc + idx * 16);
        }
        asm volatile("cp.async.commit_group;");
    }

    if (MODE == 1 && tid < DD) {
        float mu = g_sumL[l][tid] * (1.0f / NN);
        float var = g_sumsqL[l][tid] * (1.0f / NN) - mu * mu;
        float rs = rsqrtf(var + 1e-5f);
        // gamma/beta folded on host side into bias? no: passed via We/be slots
        float sc = We[tid] * rs;                 // We = gamma row
        s_scale[tid] = sc;
        s_shift[tid] = fmaf(-mu, sc, be[tid]);   // be = beta row
    }
    if (MODE == 1) __syncthreads();              // s_scale ready for fill

    // ---- A fill ----
    if (MODE == 0) {
        const float4* X4 = reinterpret_cast<const float4*>(Xin);
        float4 w4 = reinterpret_cast<const float4*>(We)[lane];
        float4 b4 = reinterpret_cast<const float4*>(be)[lane];
        float s1 = 1.0f + eps[l];
        for (int rr2 = 0; rr2 < 8; rr2++) {
            int r = wid * 8 + rr2;
            int n = tile * 64 + r;
            float4 acc = make_float4(0.f, 0.f, 0.f, 0.f);
            if (n < NN) {
                float4 hv = X4[(size_t)n * 32 + lane];
                acc.x = s1 * hv.x; acc.y = s1 * hv.y;
                acc.z = s1 * hv.z; acc.w = s1 * hv.w;
                int base = g_off[n];
                int deg = g_off[n + 1] - base;
                int i = 0;
                for (; i + 2 <= deg; i += 2) {
                    uint2 e0 = g_edges[base + i];
                    uint2 e1 = g_edges[base + i + 1];
                    float4 h0 = X4[(size_t)e0.x * 32 + lane];
                    float4 h1 = X4[(size_t)e1.x * 32 + lane];
                    float a0 = __uint_as_float(e0.y);
                    float a1 = __uint_as_float(e1.y);
                    acc.x += relu(h0.x + fmaf(a0, w4.x, b4.x)) + relu(h1.x + fmaf(a1, w4.x, b4.x));
                    acc.y += relu(h0.y + fmaf(a0, w4.y, b4.y)) + relu(h1.y + fmaf(a1, w4.y, b4.y));
                    acc.z += relu(h0.z + fmaf(a0, w4.z, b4.z)) + relu(h1.z + fmaf(a1, w4.z, b4.z));
                    acc.w += relu(h0.w + fmaf(a0, w4.w, b4.w)) + relu(h1.w + fmaf(a1, w4.w, b4.w));
                }
                if (i < deg) {
                    uint2 e0 = g_edges[base + i];
                    float4 h0 = X4[(size_t)e0.x * 32 + lane];
                    float a0 = __uint_as_float(e0.y);
                    acc.x += relu(h0.x + fmaf(a0, w4.x, b4.x));
                    acc.y += relu(h0.y + fmaf(a0, w4.y, b4.y));
                    acc.z += relu(h0.z + fmaf(a0, w4.z, b4.z));
                    acc.w += relu(h0.w + fmaf(a0, w4.w, b4.w));
                }
            }
            uint2 h2, l2;
            split2(acc.x, acc.y, h2.x, l2.x);
            split2(acc.z, acc.w, h2.y, l2.y);
            *reinterpret_cast<uint2*>(Ahi + r * RS + lane * 8) = h2;
            *reinterpret_cast<uint2*>(Ahi + ABUF + r * RS + lane * 8) = l2;
        }
    } else {
        for (int i = tid; i < 2048; i += 256) {
            int r = i >> 5, c4 = i & 31;
            int grow = tile * 64 + r;
            float4 v = make_float4(0.f, 0.f, 0.f, 0.f);
            if (grow < NN) {
                v = reinterpret_cast<const float4*>(Xin + (size_t)grow * DD)[c4];
                float4 sc = reinterpret_cast<const float4*>(s_scale)[c4];
                float4 sh = reinterpret_cast<const float4*>(s_shift)[c4];
                v.x = relu(fmaf(v.x, sc.x, sh.x));
                v.y = relu(fmaf(v.y, sc.y, sh.y));
                v.z = relu(fmaf(v.z, sc.z, sh.z));
                v.w = relu(fmaf(v.w, sc.w, sh.w));
            }
            uint2 h2, l2;
            split2(v.x, v.y, h2.x, l2.x);
            split2(v.z, v.w, h2.y, l2.y);
            *reinterpret_cast<uint2*>(Ahi + r * RS + c4 * 8) = h2;
            *reinterpret_cast<uint2*>(Ahi + ABUF + r * RS + c4 * 8) = l2;
        }
    }
    asm volatile("cp.async.wait_group 0;");
    __syncthreads();

    // ---- MMA: 8 warps, each 32 rows x 32 cols ----
    const int warp_m = wid & 1;
    const int warp_n = wid >> 1;
    const int j = lane >> 3;
    const int rr = lane & 7;
    const uint32_t sA = smem_u32(Ahi);
    const uint32_t sW = smem_u32(Whi);

    uint32_t aaddr[2];
#pragma unroll
    for (int mt = 0; mt < 2; mt++)
        aaddr[mt] = sA + (uint32_t)((warp_m * 32 + mt * 16 + (j & 1) * 8 + rr) * RS + (j >> 1) * 16);
    uint32_t baddr[2];
#pragma unroll
    for (int p = 0; p < 2; p++)
        baddr[p] = sW + (uint32_t)(((j & 1) * 8 + rr) * RS + (warp_n * 32 + p * 16 + (j >> 1) * 8) * 2);

    float acc[2][4][4];
#pragma unroll
    for (int mt = 0; mt < 2; mt++)
#pragma unroll
        for (int nt = 0; nt < 4; nt++)
#pragma unroll
            for (int q = 0; q < 4; q++) acc[mt][nt][q] = 0.0f;

#pragma unroll
    for (int ks = 0; ks < 8; ks++) {
        uint32_t ah[2][4], al[2][4], bh[2][4], bl[2][4];
#pragma unroll
        for (int mt = 0; mt < 2; mt++) {
            LDSM_X4(ah[mt], aaddr[mt]);
            LDSM_X4(al[mt], aaddr[mt] + ABUF);
            aaddr[mt] += 32;
        }
#pragma unroll
        for (int p = 0; p < 2; p++) {
            LDSM_X4_T(bh[p], baddr[p]);
            LDSM_X4_T(bl[p], baddr[p] + WBUF);
            baddr[p] += 16 * RS;
        }
#pragma unroll
        for (int mt = 0; mt < 2; mt++)
#pragma unroll
            for (int nt = 0; nt < 4; nt++) {
                const int p = nt >> 1, t2 = (nt & 1) * 2;
                MMA_BF16(acc[mt][nt], ah[mt], bh[p][t2], bh[p][t2 + 1]);
                MMA_BF16(acc[mt][nt], ah[mt], bl[p][t2], bl[p][t2 + 1]);
                MMA_BF16(acc[mt][nt], al[mt], bh[p][t2], bh[p][t2 + 1]);
            }
    }

    // ---- epilogue ----
    float* ssum = reinterpret_cast<float*>(smem);    // reuse A region
    if (MODE == 0) {
        __syncthreads();
        if (tid < 256) ssum[tid] = 0.0f;
        __syncthreads();
    }

    float sv[8], qv[8];
#pragma unroll
    for (int i = 0; i < 8; i++) { sv[i] = 0.0f; qv[i] = 0.0f; }

#pragma unroll
    for (int mt = 0; mt < 2; mt++) {
#pragma unroll
        for (int nt = 0; nt < 4; nt++) {
            int row = tile * 64 + warp_m * 32 + mt * 16 + (lane >> 2);
            int col = warp_n * 32 + nt * 8 + (lane & 3) * 2;
            float2 bv = *reinterpret_cast<const float2*>(bias + col);
#pragma unroll
            for (int hh = 0; hh < 2; hh++) {
                int grow = row + hh * 8;
                if (grow < NN) {
                    float2 o;
                    o.x = acc[mt][nt][hh * 2 + 0] + bv.x;
                    o.y = acc[mt][nt][hh * 2 + 1] + bv.y;
                    if (MODE == 0) {
                        sv[nt * 2 + 0] += o.x; qv[nt * 2 + 0] += o.x * o.x;
                        sv[nt * 2 + 1] += o.y; qv[nt * 2 + 1] += o.y * o.y;
                    } else {
                        o.x = relu(o.x); o.y = relu(o.y);
                        if (add_prev) {
                            float2 hp = *reinterpret_cast<const float2*>(
                                h_prev + (size_t)grow * DD + col);
                            o.x += hp.x; o.y += hp.y;
                        }
                    }
                    *reinterpret_cast<float2*>(out + (size_t)grow * DD + col) = o;
                }
            }
        }
    }

    if (MODE == 0) {
#pragma unroll
        for (int i = 0; i < 8; i++) {
#pragma unroll
            for (int k = 4; k < 32; k <<= 1) {
                sv[i] += __shfl_xor_sync(0xffffffff, sv[i], k);
                qv[i] += __shfl_xor_sync(0xffffffff, qv[i], k);
            }
        }
        if (lane < 4) {
#pragma unroll
            for (int i = 0; i < 8; i++) {
                int col = warp_n * 32 + (i >> 1) * 8 + lane * 2 + (i & 1);
                atomicAdd(&ssum[col], sv[i]);
                atomicAdd(&ssum[128 + col], qv[i]);
            }
        }
        __syncthreads();
        if (tid < 128) {
            atomicAdd(&g_sumL[l][tid], ssum[tid]);
            atomicAdd(&g_sumsqL[l][tid], ssum[128 + tid]);
        }
    }
}

// ---------------- launch ---------------------------------------------------
extern "C" void kernel_launch(void* const* d_in, const int* in_sizes, int n_in,
                              void* d_out, int out_size) {
    const float* x     = (const float*)d_in[0];
    const int* ei      = (const int*)d_in[1];
    const float* ea    = (const float*)d_in[2];
    const float* We    = (const float*)d_in[3];
    const float* be    = (const float*)d_in[4];
    const float* eps   = (const float*)d_in[5];
    const float* W1    = (const float*)d_in[6];
    const float* b1    = (const float*)d_in[7];
    const float* gamma = (const float*)d_in[8];
    const float* beta  = (const float*)d_in[9];
    const float* W2    = (const float*)d_in[10];
    const float* b2    = (const float*)d_in[11];
    float* out         = (float*)d_out;

    float *hbuf, *ybuf;
    cudaGetSymbolAddress((void**)&hbuf, g_h);
    cudaGetSymbolAddress((void**)&ybuf, g_y);

    cudaFuncSetAttribute(gemm_hmma_kernel<0>, cudaFuncAttributeMaxDynamicSharedMemorySize, SMEM_BYTES);
    cudaFuncSetAttribute(gemm_hmma_kernel<1>, cudaFuncAttributeMaxDynamicSharedMemorySize, SMEM_BYTES);

    const int* src = ei;
    const int* dst = ei + NE;
    const int nblk = (NN + 255) / 256;        // 391

    k_zero<<<130, 1024>>>(W1, W2);
    k_hist<<<(NE + 255) / 256, 256>>>(dst);
    k_scan1<<<nblk, 256>>>();
    k_scan2apply<<<nblk, 256>>>();
    k_fill<<<(NE + 255) / 256, 256>>>(src, dst, ea);

    for (int l = 0; l < NL; l++) {
        const float* h_in = (l == 0) ? x : hbuf;
        float* h_out = (l == NL - 1) ? out : hbuf;

        gemm_hmma_kernel<0><<<NT2, 256, SMEM_BYTES>>>(
            h_in, l * 2, b1 + l * DD, nullptr, ybuf, 0,
            eps, l, We + l * DD, be + l * DD);

        // MODE 1: gamma/beta passed through We/be params
        gemm_hmma_kernel<1><<<NT2, 256, SMEM_BYTES>>>(
            ybuf, l * 2 + 1, b2 + l * DD, hbuf, h_out,
            (l > 0) ? 1 : 0, eps, l, gamma + l * DD, beta + l * DD);
    }
}